// round 7
// baseline (speedup 1.0000x reference)
#include <cuda_runtime.h>
#include <cstdint>

#define IN_F   768
#define HID    16
#define OUTF   21
#define NMAX   50000
#define LDW    772          // padded W row stride (floats)
#define CAP    96           // bin capacity per node (deg ~ Poisson(8))

// Scratch (no cudaMalloc allowed)
__device__ float g_xp  [NMAX * HID];
__device__ float g_h1  [NMAX * HID];
__device__ float g_agg2[NMAX * HID];
__device__ int   g_cnt [NMAX];
__device__ int   g_bin [NMAX * CAP];

// ---------------- packed f32x2 helpers ----------------
__device__ __forceinline__ void ffma2(unsigned long long& acc,
                                      unsigned long long a,
                                      unsigned long long b) {
    asm("fma.rn.f32x2 %0, %1, %2, %3;" : "=l"(acc) : "l"(a), "l"(b), "l"(acc));
}
__device__ __forceinline__ unsigned long long addf2(unsigned long long a,
                                                    unsigned long long b) {
    unsigned long long r;
    asm("add.rn.f32x2 %0, %1, %2;" : "=l"(r) : "l"(a), "l"(b));
    return r;
}
__device__ __forceinline__ float2 upk(unsigned long long v) {
    float2 r;
    asm("mov.b64 {%0, %1}, %2;" : "=f"(r.x), "=f"(r.y) : "l"(v));
    return r;
}
__device__ __forceinline__ void cp16(uint32_t smem_dst, const void* gsrc) {
    asm volatile("cp.async.cg.shared.global [%0], [%1], 16;"
                 :: "r"(smem_dst), "l"(gsrc) : "memory");
}
__device__ __forceinline__ void cp_commit() {
    asm volatile("cp.async.commit_group;" ::: "memory");
}
template <int N>
__device__ __forceinline__ void cp_wait() {
    asm volatile("cp.async.wait_group %0;" :: "n"(N) : "memory");
}

// ---------------- K0: zero bin counters ----------------
__global__ void k_init(int* cnt, int n) {
    int i = blockIdx.x * blockDim.x + threadIdx.x;
    if (i < n) cnt[i] = 0;
}

// ---------------- K1: fill bins (src ids grouped by dst) ----------------
__global__ __launch_bounds__(256) void k_fill(
    const int* __restrict__ src, const int* __restrict__ dst,
    int* __restrict__ cnt, int* __restrict__ bin, int nE)
{
    int e = blockIdx.x * blockDim.x + threadIdx.x;
    if (e >= nE) return;
    int s = src[e], d = dst[e];
    int slot = atomicAdd(&cnt[d], 1);
    if (slot < CAP) bin[d * CAP + slot] = s;
}

// ---------------- K2: Xp = F @ W1  (3-buffer cp.async ring) ----------------
#define KT      64
#define NSTAGE  (IN_F / KT)              // 12
#define NBUF    3
#define W_FLTS  (HID * LDW)              // 12352
#define FBUF    (64 * KT)                // 4096 floats per buffer
#define DYNSMEM ((W_FLTS + NBUF * FBUF) * 4)

__device__ __forceinline__ void issue_stage(
    uint32_t fsh_u32, const float* Fg, int s, int tid)
{
    uint32_t dst = fsh_u32 + (uint32_t)((s % NBUF) * FBUF) * 4u;
    const float* g = Fg + s * KT;
    #pragma unroll
    for (int i = 0; i < 4; i++) {
        int idx = i * 256 + tid;
        int row = idx >> 4;
        int ch  = idx & 15;
        cp16(dst + (uint32_t)(row * KT + ch * 4) * 4u,
             g + (size_t)row * IN_F + ch * 4);
    }
    cp_commit();
}

__global__ __launch_bounds__(256, 2) void k_gemm1(
    const float* __restrict__ F, const float* __restrict__ W1,
    float* __restrict__ Xp, int nNodes)
{
    extern __shared__ float sm[];
    float* Wsh = sm;
    float* Fsh = sm + W_FLTS;

    const int tid = threadIdx.x;
    int rb = blockIdx.x * 64;
    if (rb > nNodes - 64) rb = nNodes - 64;

    const float* Fg = F + (size_t)rb * IN_F;
    uint32_t fsh_u32 = (uint32_t)__cvta_generic_to_shared(Fsh);

    // Prologue: prefetch stages 0 and 1 (distance 2), then stage W.
    issue_stage(fsh_u32, Fg, 0, tid);
    issue_stage(fsh_u32, Fg, 1, tid);

    {
        const float4* W4 = (const float4*)W1;
        for (int idx = tid; idx < (IN_F * HID) / 4; idx += 256) {
            float4 v = W4[idx];
            int k  = idx >> 2;
            int j0 = (idx & 3) * 4;
            Wsh[(j0 + 0) * LDW + k] = v.x;
            Wsh[(j0 + 1) * LDW + k] = v.y;
            Wsh[(j0 + 2) * LDW + k] = v.z;
            Wsh[(j0 + 3) * LDW + k] = v.w;
        }
    }

    const int lane = tid & 31;
    const int warp = tid >> 5;
    const int jg = lane >> 3;
    const int kg = lane & 7;
    const int j0 = jg * 4;

    unsigned long long acc[8][4];
    #pragma unroll
    for (int q = 0; q < 8; q++)
        #pragma unroll
        for (int jj = 0; jj < 4; jj++) acc[q][jj] = 0ull;

    const float* wbase = Wsh + kg * 4 + j0 * LDW;
    const float* fwarp = Fsh + warp * 8 * KT + kg * 4;

    for (int s = 0; s < NSTAGE; s++) {
        if (s + 2 < NSTAGE) {
            issue_stage(fsh_u32, Fg, s + 2, tid);
            cp_wait<2>();                 // stage s complete
        } else if (s + 1 < NSTAGE) {
            cp_wait<1>();
        } else {
            cp_wait<0>();
        }
        __syncthreads();

        const float* fs = fwarp + (s % NBUF) * FBUF;
        const float* wk = wbase + s * KT;
        #pragma unroll
        for (int k0 = 0; k0 < KT; k0 += 32) {
            ulonglong2 w[4];
            #pragma unroll
            for (int jj = 0; jj < 4; jj++)
                w[jj] = *(const ulonglong2*)(wk + jj * LDW + k0);
            #pragma unroll
            for (int q = 0; q < 8; q++) {
                ulonglong2 f = *(const ulonglong2*)(fs + q * KT + k0);
                #pragma unroll
                for (int jj = 0; jj < 4; jj++) {
                    ffma2(acc[q][jj], f.x, w[jj].x);
                    ffma2(acc[q][jj], f.y, w[jj].y);
                }
            }
        }
        __syncthreads();                  // guard buffer reuse before next issue
    }

    #pragma unroll
    for (int q = 0; q < 8; q++)
        #pragma unroll
        for (int jj = 0; jj < 4; jj++) {
            unsigned long long v = acc[q][jj];
            v = addf2(v, __shfl_xor_sync(0xffffffffu, v, 1));
            v = addf2(v, __shfl_xor_sync(0xffffffffu, v, 2));
            v = addf2(v, __shfl_xor_sync(0xffffffffu, v, 4));
            acc[q][jj] = v;
        }

    if (kg == 0) {
        int rw0 = rb + warp * 8;
        #pragma unroll
        for (int q = 0; q < 8; q++) {
            float2 a0 = upk(acc[q][0]);
            float2 a1 = upk(acc[q][1]);
            float2 a2 = upk(acc[q][2]);
            float2 a3 = upk(acc[q][3]);
            float4 o;
            o.x = a0.x + a0.y;
            o.y = a1.x + a1.y;
            o.z = a2.x + a2.y;
            o.w = a3.x + a3.y;
            *(float4*)(Xp + (size_t)(rw0 + q) * HID + j0) = o;
        }
    }
}

// ---------------- K3: gather1 -> h1 = relu(sum(Xp[bin]) + b1) ----------------
// 4 threads/node; 4-wide index prefetch for MLP.
__global__ __launch_bounds__(256) void k_gather1(
    const float* __restrict__ xin, float* __restrict__ xout,
    const int* __restrict__ cnt, const int* __restrict__ bin,
    const float* __restrict__ b1, int nNodes)
{
    int t = blockIdx.x * 256 + threadIdx.x;
    int n  = t >> 2;
    int qd = t & 3;
    if (n >= nNodes) return;

    int c = cnt[n]; if (c > CAP) c = CAP;
    const int* bp = bin + n * CAP;
    float4 acc = make_float4(0.f, 0.f, 0.f, 0.f);

    int i = 0;
    for (; i + 4 <= c; i += 4) {
        int s0 = bp[i], s1 = bp[i+1], s2 = bp[i+2], s3 = bp[i+3];
        float4 a = __ldg((const float4*)(xin + (size_t)s0 * HID) + qd);
        float4 b = __ldg((const float4*)(xin + (size_t)s1 * HID) + qd);
        float4 d = __ldg((const float4*)(xin + (size_t)s2 * HID) + qd);
        float4 e = __ldg((const float4*)(xin + (size_t)s3 * HID) + qd);
        acc.x += (a.x + b.x) + (d.x + e.x);
        acc.y += (a.y + b.y) + (d.y + e.y);
        acc.z += (a.z + b.z) + (d.z + e.z);
        acc.w += (a.w + b.w) + (d.w + e.w);
    }
    for (; i < c; i++) {
        int s0 = bp[i];
        float4 a = __ldg((const float4*)(xin + (size_t)s0 * HID) + qd);
        acc.x += a.x; acc.y += a.y; acc.z += a.z; acc.w += a.w;
    }

    float4 b = __ldg((const float4*)b1 + qd);
    float4 o;
    o.x = fmaxf(acc.x + b.x, 0.f);
    o.y = fmaxf(acc.y + b.y, 0.f);
    o.z = fmaxf(acc.z + b.z, 0.f);
    o.w = fmaxf(acc.w + b.w, 0.f);
    *((float4*)(xout + (size_t)n * HID) + qd) = o;
}

// ---------------- K4: gather2 -> agg2 = sum(h1[bin]) ----------------
__global__ __launch_bounds__(256) void k_gather2(
    const float* __restrict__ xin, float* __restrict__ xout,
    const int* __restrict__ cnt, const int* __restrict__ bin, int nNodes)
{
    int t = blockIdx.x * 256 + threadIdx.x;
    int n  = t >> 2;
    int qd = t & 3;
    if (n >= nNodes) return;

    int c = cnt[n]; if (c > CAP) c = CAP;
    const int* bp = bin + n * CAP;
    float4 acc = make_float4(0.f, 0.f, 0.f, 0.f);

    int i = 0;
    for (; i + 4 <= c; i += 4) {
        int s0 = bp[i], s1 = bp[i+1], s2 = bp[i+2], s3 = bp[i+3];
        float4 a = __ldg((const float4*)(xin + (size_t)s0 * HID) + qd);
        float4 b = __ldg((const float4*)(xin + (size_t)s1 * HID) + qd);
        float4 d = __ldg((const float4*)(xin + (size_t)s2 * HID) + qd);
        float4 e = __ldg((const float4*)(xin + (size_t)s3 * HID) + qd);
        acc.x += (a.x + b.x) + (d.x + e.x);
        acc.y += (a.y + b.y) + (d.y + e.y);
        acc.z += (a.z + b.z) + (d.z + e.z);
        acc.w += (a.w + b.w) + (d.w + e.w);
    }
    for (; i < c; i++) {
        int s0 = bp[i];
        float4 a = __ldg((const float4*)(xin + (size_t)s0 * HID) + qd);
        acc.x += a.x; acc.y += a.y; acc.z += a.z; acc.w += a.w;
    }

    *((float4*)(xout + (size_t)n * HID) + qd) = acc;
}

// ---------------- K5: out = agg2 @ W2 + b2  (16 -> 21), row per thread ----------------
__global__ __launch_bounds__(256) void k_gemm2(
    const float* __restrict__ h, const float* __restrict__ W2,
    const float* __restrict__ b2, float* __restrict__ out, int nNodes)
{
    __shared__ float Ws[HID * OUTF];
    __shared__ float bs[OUTF];
    int tid = threadIdx.x;
    for (int i = tid; i < HID * OUTF; i += 256) Ws[i] = W2[i];
    if (tid < OUTF) bs[tid] = b2[tid];
    __syncthreads();

    int r = blockIdx.x * 256 + tid;
    if (r >= nNodes) return;

    const float4* hr = (const float4*)(h + (size_t)r * HID);
    float4 h0 = __ldg(hr + 0), h1 = __ldg(hr + 1);
    float4 h2 = __ldg(hr + 2), h3 = __ldg(hr + 3);
    float hv[16] = {h0.x,h0.y,h0.z,h0.w, h1.x,h1.y,h1.z,h1.w,
                    h2.x,h2.y,h2.z,h2.w, h3.x,h3.y,h3.z,h3.w};

    float* op = out + (size_t)r * OUTF;
    #pragma unroll
    for (int j = 0; j < OUTF; j++) {
        float acc = bs[j];
        #pragma unroll
        for (int k = 0; k < HID; k++)
            acc = fmaf(hv[k], Ws[k * OUTF + j], acc);
        op[j] = acc;
    }
}

// ---------------- launch ----------------
extern "C" void kernel_launch(void* const* d_in, const int* in_sizes, int n_in,
                              void* d_out, int out_size)
{
    const float* feature = (const float*)d_in[0];
    const float* W1      = (const float*)d_in[1];
    const float* b1      = (const float*)d_in[2];
    const float* W2      = (const float*)d_in[3];
    const float* b2      = (const float*)d_in[4];
    const int*   src     = (const int*)  d_in[5];
    const int*   dst     = (const int*)  d_in[6];
    float*       out     = (float*)d_out;

    int nNodes = in_sizes[0] / IN_F;
    if (nNodes > NMAX) nNodes = NMAX;
    int nE = in_sizes[5];

    float *xp, *h1, *agg2;
    int *cnt, *bin;
    cudaGetSymbolAddress((void**)&xp,   g_xp);
    cudaGetSymbolAddress((void**)&h1,   g_h1);
    cudaGetSymbolAddress((void**)&agg2, g_agg2);
    cudaGetSymbolAddress((void**)&cnt,  g_cnt);
    cudaGetSymbolAddress((void**)&bin,  g_bin);

    static int smem_set = 0;
    if (!smem_set) {
        cudaFuncSetAttribute(k_gemm1, cudaFuncAttributeMaxDynamicSharedMemorySize,
                             DYNSMEM);
        smem_set = 1;
    }

    k_init<<<(nNodes + 255) / 256, 256>>>(cnt, nNodes);

    k_fill<<<(nE + 255) / 256, 256>>>(src, dst, cnt, bin, nE);

    k_gemm1<<<(nNodes + 63) / 64, 256, DYNSMEM>>>(feature, W1, xp, nNodes);

    int gblk = (nNodes * 4 + 255) / 256;
    k_gather1<<<gblk, 256>>>(xp, h1, cnt, bin, b1, nNodes);

    k_gather2<<<gblk, 256>>>(h1, agg2, cnt, bin, nNodes);

    k_gemm2<<<(nNodes + 255) / 256, 256>>>(agg2, W2, b2, out, nNodes);
}